// round 15
// baseline (speedup 1.0000x reference)
#include <cuda_runtime.h>
#include <math.h>

typedef unsigned long long ull;

#define NTOK    128
#define TSAMP   32768
#define KWIN    1024
#define WSTRIDE 512
#define NW      63
#define H       1024
#define G4      4096
#define ND      (NTOK*NW)      // 8064 decoder steps
#define NCTA    128
#define TPB     256
#define POLL_DELAY 260         // cycles: publish -> expected L2 visibility

// packed fp32x2 FMA (sm_103a FFMA2) — 2x fp32 throughput, PTX-only
#define FFMA2(acc, a, b) \
    asm volatile("fma.rn.f32x2 %0, %1, %2, %0;" : "+l"(acc) : "l"(a), "l"(b))
#define UNPK2(x, y, r) \
    asm volatile("mov.b64 {%0, %1}, %2;" : "=f"(x), "=f"(y) : "l"(r))
#define CVT_TF32(d, s) \
    asm volatile("cvt.rna.tf32.f32 %0, %1;" : "=r"(d) : "f"(s))

// -------- device-global scratch (static allocation is allowed) --------
__device__ float  g_C [KWIN*KWIN];     //  4 MB  cos DFT matrix
__device__ float  g_Md[G4*KWIN];       // 16 MB  Wih_d @ C
__device__ float  g_Me[G4*KWIN];       // 16 MB  Wih_e @ C
__device__ float  g_Gd[ND*G4];         // 132 MB precomputed decoder input gates (+b_d)
__device__ float  g_Ge[NW*G4];         //  1 MB  precomputed encoder input gates (+b_e)
__device__ __align__(128) float2 g_hep[2][H];  // (h, epoch) pairs, double buffered
__device__ float  g_hsave[NTOK*H];     // h at token boundaries (for logits GEMM)

// ---------------------------------------------------------------------
// Kernel 0: build cos matrix C[k][n] = cos(2*pi*k*n/1024); reset tags
// ---------------------------------------------------------------------
__global__ void fill_C() {
    int idx = blockIdx.x * 256 + threadIdx.x;
    if (idx < 2 * H) ((float2*)g_hep)[idx] = make_float2(0.0f, 0.0f);
    if (idx < KWIN * KWIN) {
        int k = idx >> 10;
        int n = idx & 1023;
        int m = (k * n) & 1023;                        // exact mod -> accurate cospif
        g_C[idx] = cospif((float)m * (1.0f / 512.0f)); // cos(2*pi*m/1024)
    }
}

#define ASTRIDE 36
#define BSTRIDE_T 136   // Bs[k][n] layout (gemm_nn: C staged untransposed)
#define BSTRIDE_N 36    // Bs[n][k] layout (gemm_win: W staged untransposed)

// convert a float4 to tf32 bit-patterns packed in a uint4
__device__ __forceinline__ uint4 cvt4_tf32(float4 v) {
    uint4 u;
    CVT_TF32(u.x, v.x); CVT_TF32(u.y, v.y);
    CVT_TF32(u.z, v.z); CVT_TF32(u.w, v.w);
    return u;
}

// ---------------------------------------------------------------------
// Kernel 1 (tf32): M = A(4096x1024) @ C(1024x1024)  (flag: 0->g_Md, 1->g_Me)
// mma.sync.m16n8k8, 128x128 tile, k-tile 32, 8 warps x (64x32).
// smem holds PRE-CONVERTED tf32 bit patterns (cvt once at staging).
// ---------------------------------------------------------------------
__global__ __launch_bounds__(256) void gemm_nn_tf32(const float* __restrict__ A, int flag) {
    float* __restrict__ D = flag ? g_Me : g_Md;

    __shared__ unsigned As[128 * ASTRIDE];     // 18 KB (tf32 bits)
    __shared__ unsigned Bs[32 * BSTRIDE_T];    // 17 KB (tf32 bits)
    int tid = threadIdx.x;
    int brow = blockIdx.y, bcol = blockIdx.x;
    int warp = tid >> 5, lane = tid & 31;
    int wm = warp >> 2, wn = warp & 3;
    int fr = lane >> 2, fc = lane & 3;

    int arow = tid >> 1;
    int akh  = (tid & 1) * 16;
    const float* pA = A + (size_t)(brow * 128 + arow) * 1024 + akh;
    int bk  = tid >> 3;
    int bnq = (tid & 7) * 16;
    const float* pC = g_C + (size_t)bk * 1024 + bcol * 128 + bnq;

    float acc[16][4];
#pragma unroll
    for (int i = 0; i < 16; i++)
#pragma unroll
        for (int c = 0; c < 4; c++) acc[i][c] = 0.0f;

    float4 a_pre[4], b_pre[4];
#pragma unroll
    for (int q = 0; q < 4; q++) {
        a_pre[q] = *(const float4*)(pA + q * 4);
        b_pre[q] = *(const float4*)(pC + q * 4);
    }

    for (int kt = 0; kt < 32; kt++) {
#pragma unroll
        for (int q = 0; q < 4; q++)
            *(uint4*)&As[arow * ASTRIDE + akh + q * 4] = cvt4_tf32(a_pre[q]);
#pragma unroll
        for (int q = 0; q < 4; q++)
            *(uint4*)&Bs[bk * BSTRIDE_T + bnq + q * 4] = cvt4_tf32(b_pre[q]);
        __syncthreads();

        if (kt < 31) {
            pA += 32; pC += (size_t)32 * 1024;
#pragma unroll
            for (int q = 0; q < 4; q++) {
                a_pre[q] = *(const float4*)(pA + q * 4);
                b_pre[q] = *(const float4*)(pC + q * 4);
            }
        }

#pragma unroll
        for (int k8 = 0; k8 < 32; k8 += 8) {
            unsigned af[4][4];
#pragma unroll
            for (int mt = 0; mt < 4; mt++) {
                int rb = wm * 64 + mt * 16;
                af[mt][0] = As[(rb + fr)     * ASTRIDE + k8 + fc];
                af[mt][1] = As[(rb + fr + 8) * ASTRIDE + k8 + fc];
                af[mt][2] = As[(rb + fr)     * ASTRIDE + k8 + fc + 4];
                af[mt][3] = As[(rb + fr + 8) * ASTRIDE + k8 + fc + 4];
            }
            unsigned bf[4][2];
#pragma unroll
            for (int nt = 0; nt < 4; nt++) {
                int cb = wn * 32 + nt * 8 + fr;
                bf[nt][0] = Bs[(k8 + fc)     * BSTRIDE_T + cb];
                bf[nt][1] = Bs[(k8 + fc + 4) * BSTRIDE_T + cb];
            }
#pragma unroll
            for (int mt = 0; mt < 4; mt++)
#pragma unroll
                for (int nt = 0; nt < 4; nt++) {
                    float* c = acc[mt * 4 + nt];
                    asm volatile(
                        "mma.sync.aligned.m16n8k8.row.col.f32.tf32.tf32.f32 "
                        "{%0,%1,%2,%3}, {%4,%5,%6,%7}, {%8,%9}, {%0,%1,%2,%3};"
                        : "+f"(c[0]), "+f"(c[1]), "+f"(c[2]), "+f"(c[3])
                        : "r"(af[mt][0]), "r"(af[mt][1]), "r"(af[mt][2]), "r"(af[mt][3]),
                          "r"(bf[nt][0]), "r"(bf[nt][1]));
                }
        }
        __syncthreads();
    }

#pragma unroll
    for (int mt = 0; mt < 4; mt++) {
#pragma unroll
        for (int nt = 0; nt < 4; nt++) {
            const float* c = acc[mt * 4 + nt];
            int row = brow * 128 + wm * 64 + mt * 16 + fr;
            int col = bcol * 128 + wn * 32 + nt * 8 + 2 * fc;
            D[(size_t)row * KWIN + col]           = c[0];
            D[(size_t)row * KWIN + col + 1]       = c[1];
            D[(size_t)(row + 8) * KWIN + col]     = c[2];
            D[(size_t)(row + 8) * KWIN + col + 1] = c[3];
        }
    }
}

// ---------------------------------------------------------------------
// Kernel 2 (tf32): G[t][r] = sum_n window(t,n)*M[r][n] + bias[r]
// Pre-converted tf32 staging; B stored [n][k] pad 36 (4 STS.128 staging).
// ---------------------------------------------------------------------
__global__ __launch_bounds__(256) void gemm_win_tf32(const float* __restrict__ x,
                                                     const float* __restrict__ bias,
                                                     int flag, int Mrows) {
    const float* __restrict__ W = flag ? g_Me : g_Md;   // 4096 x 1024
    float* __restrict__ D = flag ? g_Ge : g_Gd;

    __shared__ unsigned As[128 * ASTRIDE];     // 18 KB (tf32 bits)
    __shared__ unsigned Bs[128 * BSTRIDE_N];   // 18 KB (tf32 bits)
    int tid = threadIdx.x;
    int brow = blockIdx.y, bcol = blockIdx.x;
    int warp = tid >> 5, lane = tid & 31;
    int wm = warp >> 2, wn = warp & 3;
    int fr = lane >> 2, fc = lane & 3;

    int arow = tid >> 1;
    int akh  = (tid & 1) * 16;
    int trow = brow * 128 + arow;
    bool av = trow < Mrows;
    const float* pA = x;
    if (av) {
        int s = trow / 63;
        int w = trow - s * 63;
        pA = x + (size_t)s * TSAMP + (size_t)w * WSTRIDE + akh;
    }
    int bn  = tid & 127;
    int bkh = (tid >> 7) * 16;
    const float* pW = W + (size_t)(bcol * 128 + bn) * 1024 + bkh;

    float acc[16][4];
#pragma unroll
    for (int i = 0; i < 16; i++)
#pragma unroll
        for (int c = 0; c < 4; c++) acc[i][c] = 0.0f;

    const float4 z4 = make_float4(0.f, 0.f, 0.f, 0.f);
    float4 a_pre[4], b_pre[4];
#pragma unroll
    for (int q = 0; q < 4; q++) {
        a_pre[q] = av ? *(const float4*)(pA + q * 4) : z4;
        b_pre[q] = *(const float4*)(pW + q * 4);
    }

    for (int kt = 0; kt < 32; kt++) {
#pragma unroll
        for (int q = 0; q < 4; q++)
            *(uint4*)&As[arow * ASTRIDE + akh + q * 4] = cvt4_tf32(a_pre[q]);
#pragma unroll
        for (int q = 0; q < 4; q++)
            *(uint4*)&Bs[bn * BSTRIDE_N + bkh + q * 4] = cvt4_tf32(b_pre[q]);
        __syncthreads();

        if (kt < 31) {
            pA += 32; pW += 32;
#pragma unroll
            for (int q = 0; q < 4; q++) {
                a_pre[q] = av ? *(const float4*)(pA + q * 4) : z4;
                b_pre[q] = *(const float4*)(pW + q * 4);
            }
        }

#pragma unroll
        for (int k8 = 0; k8 < 32; k8 += 8) {
            unsigned af[4][4];
#pragma unroll
            for (int mt = 0; mt < 4; mt++) {
                int rb = wm * 64 + mt * 16;
                af[mt][0] = As[(rb + fr)     * ASTRIDE + k8 + fc];
                af[mt][1] = As[(rb + fr + 8) * ASTRIDE + k8 + fc];
                af[mt][2] = As[(rb + fr)     * ASTRIDE + k8 + fc + 4];
                af[mt][3] = As[(rb + fr + 8) * ASTRIDE + k8 + fc + 4];
            }
            unsigned bf[4][2];
#pragma unroll
            for (int nt = 0; nt < 4; nt++) {
                int cb = wn * 32 + nt * 8 + fr;
                bf[nt][0] = Bs[cb * BSTRIDE_N + k8 + fc];
                bf[nt][1] = Bs[cb * BSTRIDE_N + k8 + fc + 4];
            }
#pragma unroll
            for (int mt = 0; mt < 4; mt++)
#pragma unroll
                for (int nt = 0; nt < 4; nt++) {
                    float* c = acc[mt * 4 + nt];
                    asm volatile(
                        "mma.sync.aligned.m16n8k8.row.col.f32.tf32.tf32.f32 "
                        "{%0,%1,%2,%3}, {%4,%5,%6,%7}, {%8,%9}, {%0,%1,%2,%3};"
                        : "+f"(c[0]), "+f"(c[1]), "+f"(c[2]), "+f"(c[3])
                        : "r"(af[mt][0]), "r"(af[mt][1]), "r"(af[mt][2]), "r"(af[mt][3]),
                          "r"(bf[nt][0]), "r"(bf[nt][1]));
                }
        }
        __syncthreads();
    }

#pragma unroll
    for (int mt = 0; mt < 4; mt++) {
#pragma unroll
        for (int nt = 0; nt < 4; nt++) {
            const float* c = acc[mt * 4 + nt];
            int row = brow * 128 + wm * 64 + mt * 16 + fr;
            int col = bcol * 128 + wn * 32 + nt * 8 + 2 * fc;
            float b0v = bias[col], b1v = bias[col + 1];
            if (row < Mrows) {
                D[(size_t)row * G4 + col]     = c[0] + b0v;
                D[(size_t)row * G4 + col + 1] = c[1] + b1v;
            }
            if (row + 8 < Mrows) {
                D[(size_t)(row + 8) * G4 + col]     = c[2] + b0v;
                D[(size_t)(row + 8) * G4 + col + 1] = c[3] + b1v;
            }
        }
    }
}

// ---------------------------------------------------------------------
// Persistent sequential kernel (FROZEN — best known from R11)
// ---------------------------------------------------------------------
__device__ __forceinline__ float wredsum(float v) {
    v += __shfl_xor_sync(0xffffffffu, v, 16);
    v += __shfl_xor_sync(0xffffffffu, v, 8);
    v += __shfl_xor_sync(0xffffffffu, v, 4);
    v += __shfl_xor_sync(0xffffffffu, v, 2);
    v += __shfl_xor_sync(0xffffffffu, v, 1);
    return v;
}
__device__ __forceinline__ float sigm(float x) {
    return __fdividef(1.0f, 1.0f + __expf(-x));
}
__device__ __forceinline__ float ftanh(float x) {
    return 2.0f * __fdividef(1.0f, 1.0f + __expf(-2.0f * x)) - 1.0f;
}
__device__ __forceinline__ void stcg4(float2* p, float h0, float h1, float et) {
    asm volatile("st.global.cg.v4.f32 [%0], {%1,%2,%3,%4};"
                 :: "l"(p), "f"(h0), "f"(et), "f"(h1), "f"(et) : "memory");
}
__device__ __forceinline__ float4 ldcg4(const float2* p) {
    float4 v;
    asm volatile("ld.global.cg.v4.f32 {%0,%1,%2,%3}, [%4];"
                 : "=f"(v.x), "=f"(v.y), "=f"(v.z), "=f"(v.w) : "l"(p) : "memory");
    return v;
}

__global__ __launch_bounds__(TPB, 1) void seq_kernel(
    const float* __restrict__ Whh_e,
    const float* __restrict__ Wm1, const float* __restrict__ bm1,
    const float* __restrict__ Wm2, const float* __restrict__ bm2,
    const float* __restrict__ Whh_d)
{
    __shared__ float sh[2][H];
    __shared__ float stage[8];
    int tid  = threadIdx.x;
    int lane = tid & 31;
    int warp = tid >> 5;
    int j = blockIdx.x * 8 + warp;
    int ep = 0;
    bool own = ((tid >> 1) == blockIdx.x);

    ull wr2[64];
#pragma unroll
    for (int q = 0; q < 4; q++) {
        const ull* row = (const ull*)(Whh_d + (size_t)(q * H + j) * H);
#pragma unroll
        for (int i = 0; i < 16; i++)
            wr2[q * 16 + i] = row[lane + 32 * i];
    }

#pragma unroll
    for (int u = 0; u < 4; u++) sh[0][tid + 256 * u] = 0.0f;
    __syncthreads();
    const float* cur = sh[0];

    auto sync_collect = [&](float hnew) {
        if (lane == 0) stage[warp] = hnew;
        __syncthreads();                 // load-bearing: closes reads of sh[nb]
        ep++;
        int nb = ep & 1;
        float et = __int_as_float(ep);
        unsigned long long t0 = clock64();
        if (tid < 4)
            stcg4(&g_hep[nb][blockIdx.x * 8 + tid * 2],
                  stage[tid * 2], stage[tid * 2 + 1], et);

        float h0, h1, h2, h3;
        if (own) {
            int off = (tid & 1) * 4;
            h0 = stage[off]; h1 = stage[off + 1];
            h2 = stage[off + 2]; h3 = stage[off + 3];
        } else {
            while (clock64() - t0 < POLL_DELAY) { }
            const float2* p = &g_hep[nb][tid * 4];
            float4 va, vb;
            unsigned pend = 3u;
            do {
                if (pend & 1u) {
                    va = ldcg4(p);
                    if (__float_as_int(va.y) == ep && __float_as_int(va.w) == ep)
                        pend &= ~1u;
                }
                if (pend & 2u) {
                    vb = ldcg4(p + 2);
                    if (__float_as_int(vb.y) == ep && __float_as_int(vb.w) == ep)
                        pend &= ~2u;
                }
            } while (pend);
            h0 = va.x; h1 = va.z; h2 = vb.x; h3 = vb.z;
        }
        ((float4*)sh[nb])[tid] = make_float4(h0, h1, h2, h3);
        __syncthreads();
        cur = sh[nb];
    };

    // ================= encoder (token 0 only), 63 steps =================
    float c = 0.0f;
    const float* we0 = Whh_e + (size_t)(0 * H + j) * H + lane;
    const float* we1 = Whh_e + (size_t)(1 * H + j) * H + lane;
    const float* we2 = Whh_e + (size_t)(2 * H + j) * H + lane;
    const float* we3 = Whh_e + (size_t)(3 * H + j) * H + lane;

    for (int t = 0; t < NW; t++) {
        float a0 = 0.f, a1 = 0.f, a2 = 0.f, a3 = 0.f;
#pragma unroll
        for (int k = 0; k < 32; k++) {
            float hv = cur[k * 32 + lane];
            a0 += we0[k * 32] * hv;
            a1 += we1[k * 32] * hv;
            a2 += we2[k * 32] * hv;
            a3 += we3[k * 32] * hv;
        }
        a0 = wredsum(a0); a1 = wredsum(a1); a2 = wredsum(a2); a3 = wredsum(a3);
        const float* ge = g_Ge + (size_t)t * G4;
        float iv = sigm(a0 + ge[j]);
        float fv = sigm(a1 + ge[H + j]);
        float gv = ftanh(a2 + ge[2 * H + j]);
        float ov = sigm(a3 + ge[3 * H + j]);
        c = fv * c + iv * gv;
        float hnew = ov * ftanh(c);
        sync_collect(hnew);
    }

    // ================= mid MLP ================================
    {
        float a = 0.f;
        const float* w = Wm1 + (size_t)j * H + lane;
#pragma unroll
        for (int k = 0; k < 32; k++) a += w[k * 32] * cur[k * 32 + lane];
        a = wredsum(a) + bm1[j];
        a = fmaxf(a, 0.0f);
        sync_collect(a);
    }
    {
        float a = 0.f;
        const float* w = Wm2 + (size_t)j * H + lane;
#pragma unroll
        for (int k = 0; k < 32; k++) a += w[k * 32] * cur[k * 32 + lane];
        a = wredsum(a) + bm2[j];
        a = ftanh(a);
        sync_collect(a);
    }

    // ================= decoder: 8064 steps, h0 = c0 = h_mid ==============
    float c2 = cur[j];
    float gi = g_Gd[j], gf = g_Gd[H + j], gg = g_Gd[2 * H + j], go = g_Gd[3 * H + j];
    int wcnt = 0, tok = 0;

    for (int t = 0; t < ND; t++) {
        int tn = (t + 1 < ND) ? (t + 1) : t;
        const float* gp = g_Gd + (size_t)tn * G4;
        float ngi = gp[j], ngf = gp[H + j], ngg = gp[2 * H + j], ngo = gp[3 * H + j];

        const ull* hp = (const ull*)cur;
        ull s0 = 0ull, s1 = 0ull, s2 = 0ull, s3 = 0ull;
#pragma unroll
        for (int i = 0; i < 16; i++) {
            ull hv = hp[lane + 32 * i];
            FFMA2(s0, wr2[i],      hv);
            FFMA2(s1, wr2[16 + i], hv);
            FFMA2(s2, wr2[32 + i], hv);
            FFMA2(s3, wr2[48 + i], hv);
        }
        float a0, a1, a2, a3, xl, xh;
        UNPK2(xl, xh, s0); a0 = xl + xh;
        UNPK2(xl, xh, s1); a1 = xl + xh;
        UNPK2(xl, xh, s2); a2 = xl + xh;
        UNPK2(xl, xh, s3); a3 = xl + xh;
        a0 = wredsum(a0); a1 = wredsum(a1); a2 = wredsum(a2); a3 = wredsum(a3);
        float iv = sigm(a0 + gi);
        float fv = sigm(a1 + gf);
        float gv = ftanh(a2 + gg);
        float ov = sigm(a3 + go);
        c2 = fv * c2 + iv * gv;
        float hnew = ov * ftanh(c2);
        gi = ngi; gf = ngf; gg = ngg; go = ngo;

        if (++wcnt == 63) {
            wcnt = 0;
            if (lane == 0) g_hsave[(size_t)tok * H + j] = hnew;
            tok++;
        }

        sync_collect(hnew);
    }
}

// ---------------------------------------------------------------------
// Final: logits = Hsave @ Wo^T + bo, fused log_softmax, 1 CTA per token
// ---------------------------------------------------------------------
__global__ __launch_bounds__(256) void lsm_kernel(const float* __restrict__ Wo,
                                                  const float* __restrict__ bo,
                                                  float* __restrict__ out) {
    __shared__ float hrow[H];
    __shared__ float sred[8];
    int tid = threadIdx.x, lane = tid & 31, warp = tid >> 5;

    *(float4*)&hrow[tid * 4] = *(const float4*)&g_hsave[(size_t)blockIdx.x * H + tid * 4];
    __syncthreads();

    const ull* hp = (const ull*)hrow;
    float v[4];
#pragma unroll
    for (int u = 0; u < 4; u++) {
        int cidx = tid + 256 * u;
        const ull* wp = (const ull*)(Wo + (size_t)cidx * H);
        ull acc = 0ull;
#pragma unroll 8
        for (int k2 = 0; k2 < 512; k2++) FFMA2(acc, wp[k2], hp[k2]);
        float lo, hi; UNPK2(lo, hi, acc);
        v[u] = lo + hi + bo[cidx];
    }

    float m = -1e30f;
#pragma unroll
    for (int u = 0; u < 4; u++) m = fmaxf(m, v[u]);
#pragma unroll
    for (int off = 16; off; off >>= 1) m = fmaxf(m, __shfl_xor_sync(0xffffffffu, m, off));
    if (lane == 0) sred[warp] = m;
    __syncthreads();
    if (tid == 0) {
        float mm = sred[0];
        for (int w = 1; w < 8; w++) mm = fmaxf(mm, sred[w]);
        sred[0] = mm;
    }
    __syncthreads();
    m = sred[0];
    __syncthreads();
    float s = 0.f;
#pragma unroll
    for (int u = 0; u < 4; u++) s += __expf(v[u] - m);
#pragma unroll
    for (int off = 16; off; off >>= 1) s += __shfl_xor_sync(0xffffffffu, s, off);
    if (lane == 0) sred[warp] = s;
    __syncthreads();
    if (tid == 0) {
        float st = 0.f;
        for (int w = 0; w < 8; w++) st += sred[w];
        sred[0] = st;
    }
    __syncthreads();
    float l = m + logf(sred[0]);
    float* z = out + (size_t)blockIdx.x * H;
#pragma unroll
    for (int u = 0; u < 4; u++) z[tid + 256 * u] = v[u] - l;
}

// ---------------------------------------------------------------------
extern "C" void kernel_launch(void* const* d_in, const int* in_sizes, int n_in,
                              void* d_out, int out_size) {
    const float* x     = (const float*)d_in[0];
    const float* Wih_e = (const float*)d_in[1];
    const float* Whh_e = (const float*)d_in[2];
    const float* b_e   = (const float*)d_in[3];
    const float* Wm1   = (const float*)d_in[4];
    const float* bm1   = (const float*)d_in[5];
    const float* Wm2   = (const float*)d_in[6];
    const float* bm2   = (const float*)d_in[7];
    const float* Wih_d = (const float*)d_in[8];
    const float* Whh_d = (const float*)d_in[9];
    const float* b_d   = (const float*)d_in[10];
    const float* Wo    = (const float*)d_in[11];
    const float* bo    = (const float*)d_in[12];
    float* out = (float*)d_out;

    // 0) cos matrix + tag reset (both needed every replay)
    fill_C<<<4096, 256>>>();

    // 1) fold DFT into input projections via tf32 tensor cores
    gemm_nn_tf32<<<dim3(KWIN / 128, G4 / 128), 256>>>(Wih_d, 0);  // -> g_Md
    gemm_nn_tf32<<<dim3(KWIN / 128, G4 / 128), 256>>>(Wih_e, 1);  // -> g_Me

    // 2) precompute all input gates via tf32 tensor cores
    gemm_win_tf32<<<dim3(G4 / 128, ND / 128), 256>>>(x, b_d, 0, ND);  // -> g_Gd
    gemm_win_tf32<<<dim3(G4 / 128, 1),        256>>>(x, b_e, 1, NW);  // -> g_Ge

    // 3) sequential encoder + MLP + decoder (persistent, delayed-poll sync)
    seq_kernel<<<NCTA, TPB>>>(Whh_e, Wm1, bm1, Wm2, bm2, Whh_d);

    // 4) logits GEMM + log_softmax per token
    lsm_kernel<<<NTOK, 256>>>(Wo, bo, out);
}

// round 16
// speedup vs baseline: 1.0182x; 1.0182x over previous
#include <cuda_runtime.h>
#include <math.h>

typedef unsigned long long ull;

#define NTOK    128
#define TSAMP   32768
#define KWIN    1024
#define WSTRIDE 512
#define NW      63
#define H       1024
#define G4      4096
#define ND      (NTOK*NW)      // 8064 decoder steps
#define NCTA    128
#define TPB     256
#define POLL_DELAY 260         // cycles: publish -> expected L2 visibility

// packed fp32x2 FMA (sm_103a FFMA2) — 2x fp32 throughput, PTX-only
#define FFMA2(acc, a, b) \
    asm volatile("fma.rn.f32x2 %0, %1, %2, %0;" : "+l"(acc) : "l"(a), "l"(b))
#define UNPK2(x, y, r) \
    asm volatile("mov.b64 {%0, %1}, %2;" : "=f"(x), "=f"(y) : "l"(r))
#define CVT_TF32(d, s) \
    asm volatile("cvt.rna.tf32.f32 %0, %1;" : "=r"(d) : "f"(s))

// -------- device-global scratch (static allocation is allowed) --------
__device__ float  g_C [KWIN*KWIN];     //  4 MB  cos DFT matrix
__device__ float  g_Md[G4*KWIN];       // 16 MB  Wih_d @ C
__device__ float  g_Me[G4*KWIN];       // 16 MB  Wih_e @ C
__device__ float  g_Gd[ND*G4];         // 132 MB precomputed decoder input gates (+b_d)
__device__ float  g_Ge[NW*G4];         //  1 MB  precomputed encoder input gates (+b_e)
__device__ __align__(128) float2 g_hep[2][H];  // (h, epoch) pairs, double buffered
__device__ float  g_hsave[NTOK*H];     // h at token boundaries (for logits GEMM)

// ---------------------------------------------------------------------
// Kernel 0: build cos matrix C[k][n] = cos(2*pi*k*n/1024); reset tags
// ---------------------------------------------------------------------
__global__ void fill_C() {
    int idx = blockIdx.x * 256 + threadIdx.x;
    if (idx < 2 * H) ((float2*)g_hep)[idx] = make_float2(0.0f, 0.0f);
    if (idx < KWIN * KWIN) {
        int k = idx >> 10;
        int n = idx & 1023;
        int m = (k * n) & 1023;                        // exact mod -> accurate cospif
        g_C[idx] = cospif((float)m * (1.0f / 512.0f)); // cos(2*pi*m/1024)
    }
}

#define ASTRIDE 36
#define BSTRIDE_T 136   // Bs[k][n] layout (gemm_nn: C staged untransposed)
#define BSTRIDE_N 36    // Bs[n][k] layout (gemm_win: W staged untransposed)

// convert a float4 to tf32 bit-patterns packed in a uint4
__device__ __forceinline__ uint4 cvt4_tf32(float4 v) {
    uint4 u;
    CVT_TF32(u.x, v.x); CVT_TF32(u.y, v.y);
    CVT_TF32(u.z, v.z); CVT_TF32(u.w, v.w);
    return u;
}

// ---------------------------------------------------------------------
// Kernel 1 (tf32): M = A(4096x1024) @ C(1024x1024)  (flag: 0->g_Md, 1->g_Me)
// mma.sync.m16n8k8, 128x128 tile, k-tile 32, 8 warps x (64x32).
// Pre-converted tf32 staging; 2 CTAs/SM for issue-bubble filling.
// ---------------------------------------------------------------------
__global__ __launch_bounds__(256, 2) void gemm_nn_tf32(const float* __restrict__ A, int flag) {
    float* __restrict__ D = flag ? g_Me : g_Md;

    __shared__ unsigned As[128 * ASTRIDE];     // 18 KB (tf32 bits)
    __shared__ unsigned Bs[32 * BSTRIDE_T];    // 17 KB (tf32 bits)
    int tid = threadIdx.x;
    int brow = blockIdx.y, bcol = blockIdx.x;
    int warp = tid >> 5, lane = tid & 31;
    int wm = warp >> 2, wn = warp & 3;
    int fr = lane >> 2, fc = lane & 3;

    int arow = tid >> 1;
    int akh  = (tid & 1) * 16;
    const float* pA = A + (size_t)(brow * 128 + arow) * 1024 + akh;
    int bk  = tid >> 3;
    int bnq = (tid & 7) * 16;
    const float* pC = g_C + (size_t)bk * 1024 + bcol * 128 + bnq;

    float acc[16][4];
#pragma unroll
    for (int i = 0; i < 16; i++)
#pragma unroll
        for (int c = 0; c < 4; c++) acc[i][c] = 0.0f;

    float4 a_pre[4], b_pre[4];
#pragma unroll
    for (int q = 0; q < 4; q++) {
        a_pre[q] = *(const float4*)(pA + q * 4);
        b_pre[q] = *(const float4*)(pC + q * 4);
    }

    for (int kt = 0; kt < 32; kt++) {
#pragma unroll
        for (int q = 0; q < 4; q++)
            *(uint4*)&As[arow * ASTRIDE + akh + q * 4] = cvt4_tf32(a_pre[q]);
#pragma unroll
        for (int q = 0; q < 4; q++)
            *(uint4*)&Bs[bk * BSTRIDE_T + bnq + q * 4] = cvt4_tf32(b_pre[q]);
        __syncthreads();

        if (kt < 31) {
            pA += 32; pC += (size_t)32 * 1024;
#pragma unroll
            for (int q = 0; q < 4; q++) {
                a_pre[q] = *(const float4*)(pA + q * 4);
                b_pre[q] = *(const float4*)(pC + q * 4);
            }
        }

#pragma unroll
        for (int k8 = 0; k8 < 32; k8 += 8) {
            unsigned af[4][4];
#pragma unroll
            for (int mt = 0; mt < 4; mt++) {
                int rb = wm * 64 + mt * 16;
                af[mt][0] = As[(rb + fr)     * ASTRIDE + k8 + fc];
                af[mt][1] = As[(rb + fr + 8) * ASTRIDE + k8 + fc];
                af[mt][2] = As[(rb + fr)     * ASTRIDE + k8 + fc + 4];
                af[mt][3] = As[(rb + fr + 8) * ASTRIDE + k8 + fc + 4];
            }
            unsigned bf[4][2];
#pragma unroll
            for (int nt = 0; nt < 4; nt++) {
                int cb = wn * 32 + nt * 8 + fr;
                bf[nt][0] = Bs[(k8 + fc)     * BSTRIDE_T + cb];
                bf[nt][1] = Bs[(k8 + fc + 4) * BSTRIDE_T + cb];
            }
#pragma unroll
            for (int mt = 0; mt < 4; mt++)
#pragma unroll
                for (int nt = 0; nt < 4; nt++) {
                    float* c = acc[mt * 4 + nt];
                    asm volatile(
                        "mma.sync.aligned.m16n8k8.row.col.f32.tf32.tf32.f32 "
                        "{%0,%1,%2,%3}, {%4,%5,%6,%7}, {%8,%9}, {%0,%1,%2,%3};"
                        : "+f"(c[0]), "+f"(c[1]), "+f"(c[2]), "+f"(c[3])
                        : "r"(af[mt][0]), "r"(af[mt][1]), "r"(af[mt][2]), "r"(af[mt][3]),
                          "r"(bf[nt][0]), "r"(bf[nt][1]));
                }
        }
        __syncthreads();
    }

#pragma unroll
    for (int mt = 0; mt < 4; mt++) {
#pragma unroll
        for (int nt = 0; nt < 4; nt++) {
            const float* c = acc[mt * 4 + nt];
            int row = brow * 128 + wm * 64 + mt * 16 + fr;
            int col = bcol * 128 + wn * 32 + nt * 8 + 2 * fc;
            D[(size_t)row * KWIN + col]           = c[0];
            D[(size_t)row * KWIN + col + 1]       = c[1];
            D[(size_t)(row + 8) * KWIN + col]     = c[2];
            D[(size_t)(row + 8) * KWIN + col + 1] = c[3];
        }
    }
}

// ---------------------------------------------------------------------
// Kernel 2 (tf32): G[t][r] = sum_n window(t,n)*M[r][n] + bias[r]
// Pre-converted tf32 staging; B stored [n][k] pad 36; 2 CTAs/SM.
// ---------------------------------------------------------------------
__global__ __launch_bounds__(256, 2) void gemm_win_tf32(const float* __restrict__ x,
                                                        const float* __restrict__ bias,
                                                        int flag, int Mrows) {
    const float* __restrict__ W = flag ? g_Me : g_Md;   // 4096 x 1024
    float* __restrict__ D = flag ? g_Ge : g_Gd;

    __shared__ unsigned As[128 * ASTRIDE];     // 18 KB (tf32 bits)
    __shared__ unsigned Bs[128 * BSTRIDE_N];   // 18 KB (tf32 bits)
    int tid = threadIdx.x;
    int brow = blockIdx.y, bcol = blockIdx.x;
    int warp = tid >> 5, lane = tid & 31;
    int wm = warp >> 2, wn = warp & 3;
    int fr = lane >> 2, fc = lane & 3;

    int arow = tid >> 1;
    int akh  = (tid & 1) * 16;
    int trow = brow * 128 + arow;
    bool av = trow < Mrows;
    const float* pA = x;
    if (av) {
        int s = trow / 63;
        int w = trow - s * 63;
        pA = x + (size_t)s * TSAMP + (size_t)w * WSTRIDE + akh;
    }
    int bn  = tid & 127;
    int bkh = (tid >> 7) * 16;
    const float* pW = W + (size_t)(bcol * 128 + bn) * 1024 + bkh;

    float acc[16][4];
#pragma unroll
    for (int i = 0; i < 16; i++)
#pragma unroll
        for (int c = 0; c < 4; c++) acc[i][c] = 0.0f;

    const float4 z4 = make_float4(0.f, 0.f, 0.f, 0.f);
    float4 a_pre[4], b_pre[4];
#pragma unroll
    for (int q = 0; q < 4; q++) {
        a_pre[q] = av ? *(const float4*)(pA + q * 4) : z4;
        b_pre[q] = *(const float4*)(pW + q * 4);
    }

    for (int kt = 0; kt < 32; kt++) {
#pragma unroll
        for (int q = 0; q < 4; q++)
            *(uint4*)&As[arow * ASTRIDE + akh + q * 4] = cvt4_tf32(a_pre[q]);
#pragma unroll
        for (int q = 0; q < 4; q++)
            *(uint4*)&Bs[bn * BSTRIDE_N + bkh + q * 4] = cvt4_tf32(b_pre[q]);
        __syncthreads();

        if (kt < 31) {
            pA += 32; pW += 32;
#pragma unroll
            for (int q = 0; q < 4; q++) {
                a_pre[q] = av ? *(const float4*)(pA + q * 4) : z4;
                b_pre[q] = *(const float4*)(pW + q * 4);
            }
        }

#pragma unroll
        for (int k8 = 0; k8 < 32; k8 += 8) {
            unsigned af[4][4];
#pragma unroll
            for (int mt = 0; mt < 4; mt++) {
                int rb = wm * 64 + mt * 16;
                af[mt][0] = As[(rb + fr)     * ASTRIDE + k8 + fc];
                af[mt][1] = As[(rb + fr + 8) * ASTRIDE + k8 + fc];
                af[mt][2] = As[(rb + fr)     * ASTRIDE + k8 + fc + 4];
                af[mt][3] = As[(rb + fr + 8) * ASTRIDE + k8 + fc + 4];
            }
            unsigned bf[4][2];
#pragma unroll
            for (int nt = 0; nt < 4; nt++) {
                int cb = wn * 32 + nt * 8 + fr;
                bf[nt][0] = Bs[cb * BSTRIDE_N + k8 + fc];
                bf[nt][1] = Bs[cb * BSTRIDE_N + k8 + fc + 4];
            }
#pragma unroll
            for (int mt = 0; mt < 4; mt++)
#pragma unroll
                for (int nt = 0; nt < 4; nt++) {
                    float* c = acc[mt * 4 + nt];
                    asm volatile(
                        "mma.sync.aligned.m16n8k8.row.col.f32.tf32.tf32.f32 "
                        "{%0,%1,%2,%3}, {%4,%5,%6,%7}, {%8,%9}, {%0,%1,%2,%3};"
                        : "+f"(c[0]), "+f"(c[1]), "+f"(c[2]), "+f"(c[3])
                        : "r"(af[mt][0]), "r"(af[mt][1]), "r"(af[mt][2]), "r"(af[mt][3]),
                          "r"(bf[nt][0]), "r"(bf[nt][1]));
                }
        }
        __syncthreads();
    }

#pragma unroll
    for (int mt = 0; mt < 4; mt++) {
#pragma unroll
        for (int nt = 0; nt < 4; nt++) {
            const float* c = acc[mt * 4 + nt];
            int row = brow * 128 + wm * 64 + mt * 16 + fr;
            int col = bcol * 128 + wn * 32 + nt * 8 + 2 * fc;
            float b0v = bias[col], b1v = bias[col + 1];
            if (row < Mrows) {
                D[(size_t)row * G4 + col]     = c[0] + b0v;
                D[(size_t)row * G4 + col + 1] = c[1] + b1v;
            }
            if (row + 8 < Mrows) {
                D[(size_t)(row + 8) * G4 + col]     = c[2] + b0v;
                D[(size_t)(row + 8) * G4 + col + 1] = c[3] + b1v;
            }
        }
    }
}

// ---------------------------------------------------------------------
// Persistent sequential kernel (FROZEN — best known from R11)
// ---------------------------------------------------------------------
__device__ __forceinline__ float wredsum(float v) {
    v += __shfl_xor_sync(0xffffffffu, v, 16);
    v += __shfl_xor_sync(0xffffffffu, v, 8);
    v += __shfl_xor_sync(0xffffffffu, v, 4);
    v += __shfl_xor_sync(0xffffffffu, v, 2);
    v += __shfl_xor_sync(0xffffffffu, v, 1);
    return v;
}
__device__ __forceinline__ float sigm(float x) {
    return __fdividef(1.0f, 1.0f + __expf(-x));
}
__device__ __forceinline__ float ftanh(float x) {
    return 2.0f * __fdividef(1.0f, 1.0f + __expf(-2.0f * x)) - 1.0f;
}
__device__ __forceinline__ void stcg4(float2* p, float h0, float h1, float et) {
    asm volatile("st.global.cg.v4.f32 [%0], {%1,%2,%3,%4};"
                 :: "l"(p), "f"(h0), "f"(et), "f"(h1), "f"(et) : "memory");
}
__device__ __forceinline__ float4 ldcg4(const float2* p) {
    float4 v;
    asm volatile("ld.global.cg.v4.f32 {%0,%1,%2,%3}, [%4];"
                 : "=f"(v.x), "=f"(v.y), "=f"(v.z), "=f"(v.w) : "l"(p) : "memory");
    return v;
}

__global__ __launch_bounds__(TPB, 1) void seq_kernel(
    const float* __restrict__ Whh_e,
    const float* __restrict__ Wm1, const float* __restrict__ bm1,
    const float* __restrict__ Wm2, const float* __restrict__ bm2,
    const float* __restrict__ Whh_d)
{
    __shared__ float sh[2][H];
    __shared__ float stage[8];
    int tid  = threadIdx.x;
    int lane = tid & 31;
    int warp = tid >> 5;
    int j = blockIdx.x * 8 + warp;
    int ep = 0;
    bool own = ((tid >> 1) == blockIdx.x);

    ull wr2[64];
#pragma unroll
    for (int q = 0; q < 4; q++) {
        const ull* row = (const ull*)(Whh_d + (size_t)(q * H + j) * H);
#pragma unroll
        for (int i = 0; i < 16; i++)
            wr2[q * 16 + i] = row[lane + 32 * i];
    }

#pragma unroll
    for (int u = 0; u < 4; u++) sh[0][tid + 256 * u] = 0.0f;
    __syncthreads();
    const float* cur = sh[0];

    auto sync_collect = [&](float hnew) {
        if (lane == 0) stage[warp] = hnew;
        __syncthreads();                 // load-bearing: closes reads of sh[nb]
        ep++;
        int nb = ep & 1;
        float et = __int_as_float(ep);
        unsigned long long t0 = clock64();
        if (tid < 4)
            stcg4(&g_hep[nb][blockIdx.x * 8 + tid * 2],
                  stage[tid * 2], stage[tid * 2 + 1], et);

        float h0, h1, h2, h3;
        if (own) {
            int off = (tid & 1) * 4;
            h0 = stage[off]; h1 = stage[off + 1];
            h2 = stage[off + 2]; h3 = stage[off + 3];
        } else {
            while (clock64() - t0 < POLL_DELAY) { }
            const float2* p = &g_hep[nb][tid * 4];
            float4 va, vb;
            unsigned pend = 3u;
            do {
                if (pend & 1u) {
                    va = ldcg4(p);
                    if (__float_as_int(va.y) == ep && __float_as_int(va.w) == ep)
                        pend &= ~1u;
                }
                if (pend & 2u) {
                    vb = ldcg4(p + 2);
                    if (__float_as_int(vb.y) == ep && __float_as_int(vb.w) == ep)
                        pend &= ~2u;
                }
            } while (pend);
            h0 = va.x; h1 = va.z; h2 = vb.x; h3 = vb.z;
        }
        ((float4*)sh[nb])[tid] = make_float4(h0, h1, h2, h3);
        __syncthreads();
        cur = sh[nb];
    };

    // ================= encoder (token 0 only), 63 steps =================
    float c = 0.0f;
    const float* we0 = Whh_e + (size_t)(0 * H + j) * H + lane;
    const float* we1 = Whh_e + (size_t)(1 * H + j) * H + lane;
    const float* we2 = Whh_e + (size_t)(2 * H + j) * H + lane;
    const float* we3 = Whh_e + (size_t)(3 * H + j) * H + lane;

    for (int t = 0; t < NW; t++) {
        float a0 = 0.f, a1 = 0.f, a2 = 0.f, a3 = 0.f;
#pragma unroll
        for (int k = 0; k < 32; k++) {
            float hv = cur[k * 32 + lane];
            a0 += we0[k * 32] * hv;
            a1 += we1[k * 32] * hv;
            a2 += we2[k * 32] * hv;
            a3 += we3[k * 32] * hv;
        }
        a0 = wredsum(a0); a1 = wredsum(a1); a2 = wredsum(a2); a3 = wredsum(a3);
        const float* ge = g_Ge + (size_t)t * G4;
        float iv = sigm(a0 + ge[j]);
        float fv = sigm(a1 + ge[H + j]);
        float gv = ftanh(a2 + ge[2 * H + j]);
        float ov = sigm(a3 + ge[3 * H + j]);
        c = fv * c + iv * gv;
        float hnew = ov * ftanh(c);
        sync_collect(hnew);
    }

    // ================= mid MLP ================================
    {
        float a = 0.f;
        const float* w = Wm1 + (size_t)j * H + lane;
#pragma unroll
        for (int k = 0; k < 32; k++) a += w[k * 32] * cur[k * 32 + lane];
        a = wredsum(a) + bm1[j];
        a = fmaxf(a, 0.0f);
        sync_collect(a);
    }
    {
        float a = 0.f;
        const float* w = Wm2 + (size_t)j * H + lane;
#pragma unroll
        for (int k = 0; k < 32; k++) a += w[k * 32] * cur[k * 32 + lane];
        a = wredsum(a) + bm2[j];
        a = ftanh(a);
        sync_collect(a);
    }

    // ================= decoder: 8064 steps, h0 = c0 = h_mid ==============
    float c2 = cur[j];
    float gi = g_Gd[j], gf = g_Gd[H + j], gg = g_Gd[2 * H + j], go = g_Gd[3 * H + j];
    int wcnt = 0, tok = 0;

    for (int t = 0; t < ND; t++) {
        int tn = (t + 1 < ND) ? (t + 1) : t;
        const float* gp = g_Gd + (size_t)tn * G4;
        float ngi = gp[j], ngf = gp[H + j], ngg = gp[2 * H + j], ngo = gp[3 * H + j];

        const ull* hp = (const ull*)cur;
        ull s0 = 0ull, s1 = 0ull, s2 = 0ull, s3 = 0ull;
#pragma unroll
        for (int i = 0; i < 16; i++) {
            ull hv = hp[lane + 32 * i];
            FFMA2(s0, wr2[i],      hv);
            FFMA2(s1, wr2[16 + i], hv);
            FFMA2(s2, wr2[32 + i], hv);
            FFMA2(s3, wr2[48 + i], hv);
        }
        float a0, a1, a2, a3, xl, xh;
        UNPK2(xl, xh, s0); a0 = xl + xh;
        UNPK2(xl, xh, s1); a1 = xl + xh;
        UNPK2(xl, xh, s2); a2 = xl + xh;
        UNPK2(xl, xh, s3); a3 = xl + xh;
        a0 = wredsum(a0); a1 = wredsum(a1); a2 = wredsum(a2); a3 = wredsum(a3);
        float iv = sigm(a0 + gi);
        float fv = sigm(a1 + gf);
        float gv = ftanh(a2 + gg);
        float ov = sigm(a3 + go);
        c2 = fv * c2 + iv * gv;
        float hnew = ov * ftanh(c2);
        gi = ngi; gf = ngf; gg = ngg; go = ngo;

        if (++wcnt == 63) {
            wcnt = 0;
            if (lane == 0) g_hsave[(size_t)tok * H + j] = hnew;
            tok++;
        }

        sync_collect(hnew);
    }
}

// ---------------------------------------------------------------------
// Final: logits = Hsave @ Wo^T + bo, fused log_softmax, 1 CTA per token
// ---------------------------------------------------------------------
__global__ __launch_bounds__(256) void lsm_kernel(const float* __restrict__ Wo,
                                                  const float* __restrict__ bo,
                                                  float* __restrict__ out) {
    __shared__ float hrow[H];
    __shared__ float sred[8];
    int tid = threadIdx.x, lane = tid & 31, warp = tid >> 5;

    *(float4*)&hrow[tid * 4] = *(const float4*)&g_hsave[(size_t)blockIdx.x * H + tid * 4];
    __syncthreads();

    const ull* hp = (const ull*)hrow;
    float v[4];
#pragma unroll
    for (int u = 0; u < 4; u++) {
        int cidx = tid + 256 * u;
        const ull* wp = (const ull*)(Wo + (size_t)cidx * H);
        ull acc = 0ull;
#pragma unroll 8
        for (int k2 = 0; k2 < 512; k2++) FFMA2(acc, wp[k2], hp[k2]);
        float lo, hi; UNPK2(lo, hi, acc);
        v[u] = lo + hi + bo[cidx];
    }

    float m = -1e30f;
#pragma unroll
    for (int u = 0; u < 4; u++) m = fmaxf(m, v[u]);
#pragma unroll
    for (int off = 16; off; off >>= 1) m = fmaxf(m, __shfl_xor_sync(0xffffffffu, m, off));
    if (lane == 0) sred[warp] = m;
    __syncthreads();
    if (tid == 0) {
        float mm = sred[0];
        for (int w = 1; w < 8; w++) mm = fmaxf(mm, sred[w]);
        sred[0] = mm;
    }
    __syncthreads();
    m = sred[0];
    __syncthreads();
    float s = 0.f;
#pragma unroll
    for (int u = 0; u < 4; u++) s += __expf(v[u] - m);
#pragma unroll
    for (int off = 16; off; off >>= 1) s += __shfl_xor_sync(0xffffffffu, s, off);
    if (lane == 0) sred[warp] = s;
    __syncthreads();
    if (tid == 0) {
        float st = 0.f;
        for (int w = 0; w < 8; w++) st += sred[w];
        sred[0] = st;
    }
    __syncthreads();
    float l = m + logf(sred[0]);
    float* z = out + (size_t)blockIdx.x * H;
#pragma unroll
    for (int u = 0; u < 4; u++) z[tid + 256 * u] = v[u] - l;
}

// ---------------------------------------------------------------------
extern "C" void kernel_launch(void* const* d_in, const int* in_sizes, int n_in,
                              void* d_out, int out_size) {
    const float* x     = (const float*)d_in[0];
    const float* Wih_e = (const float*)d_in[1];
    const float* Whh_e = (const float*)d_in[2];
    const float* b_e   = (const float*)d_in[3];
    const float* Wm1   = (const float*)d_in[4];
    const float* bm1   = (const float*)d_in[5];
    const float* Wm2   = (const float*)d_in[6];
    const float* bm2   = (const float*)d_in[7];
    const float* Wih_d = (const float*)d_in[8];
    const float* Whh_d = (const float*)d_in[9];
    const float* b_d   = (const float*)d_in[10];
    const float* Wo    = (const float*)d_in[11];
    const float* bo    = (const float*)d_in[12];
    float* out = (float*)d_out;

    // 0) cos matrix + tag reset (both needed every replay)
    fill_C<<<4096, 256>>>();

    // 1) fold DFT into input projections via tf32 tensor cores
    gemm_nn_tf32<<<dim3(KWIN / 128, G4 / 128), 256>>>(Wih_d, 0);  // -> g_Md
    gemm_nn_tf32<<<dim3(KWIN / 128, G4 / 128), 256>>>(Wih_e, 1);  // -> g_Me

    // 2) precompute all input gates via tf32 tensor cores
    gemm_win_tf32<<<dim3(G4 / 128, ND / 128), 256>>>(x, b_d, 0, ND);  // -> g_Gd
    gemm_win_tf32<<<dim3(G4 / 128, 1),        256>>>(x, b_e, 1, NW);  // -> g_Ge

    // 3) sequential encoder + MLP + decoder (persistent, delayed-poll sync)
    seq_kernel<<<NCTA, TPB>>>(Whh_e, Wm1, bm1, Wm2, bm2, Whh_d);

    // 4) logits GEMM + log_softmax per token
    lsm_kernel<<<NTOK, 256>>>(Wo, bo, out);
}

// round 17
// speedup vs baseline: 1.0248x; 1.0065x over previous
#include <cuda_runtime.h>
#include <math.h>

typedef unsigned long long ull;

#define NTOK    128
#define TSAMP   32768
#define KWIN    1024
#define WSTRIDE 512
#define NW      63
#define H       1024
#define G4      4096
#define ND      (NTOK*NW)      // 8064 decoder steps
#define NCTA    128
#define TPB     256
#define POLL_DELAY 260         // cycles: publish -> expected L2 visibility

// packed fp32x2 FMA (sm_103a FFMA2) — 2x fp32 throughput, PTX-only
#define FFMA2(acc, a, b) \
    asm volatile("fma.rn.f32x2 %0, %1, %2, %0;" : "+l"(acc) : "l"(a), "l"(b))
#define UNPK2(x, y, r) \
    asm volatile("mov.b64 {%0, %1}, %2;" : "=f"(x), "=f"(y) : "l"(r))
#define CVT_TF32(d, s) \
    asm volatile("cvt.rna.tf32.f32 %0, %1;" : "=r"(d) : "f"(s))

// -------- device-global scratch (static allocation is allowed) --------
__device__ float  g_C [KWIN*KWIN];     //  4 MB  cos DFT matrix
__device__ float  g_Md[G4*KWIN];       // 16 MB  Wih_d @ C
__device__ float  g_Me[G4*KWIN];       // 16 MB  Wih_e @ C
__device__ float  g_Gd[ND*G4];         // 132 MB precomputed decoder input gates (+b_d)
__device__ float  g_Ge[NW*G4];         //  1 MB  precomputed encoder input gates (+b_e)
__device__ __align__(128) float2 g_hep[2][H];  // (h, epoch) pairs, double buffered
__device__ float  g_hsave[NTOK*H];     // h at token boundaries (for logits GEMM)

// ---------------------------------------------------------------------
// Kernel 0: build cos matrix C[k][n] = cos(2*pi*k*n/1024); reset tags
// ---------------------------------------------------------------------
__global__ void fill_C() {
    int idx = blockIdx.x * 256 + threadIdx.x;
    if (idx < 2 * H) ((float2*)g_hep)[idx] = make_float2(0.0f, 0.0f);
    if (idx < KWIN * KWIN) {
        int k = idx >> 10;
        int n = idx & 1023;
        int m = (k * n) & 1023;                        // exact mod -> accurate cospif
        g_C[idx] = cospif((float)m * (1.0f / 512.0f)); // cos(2*pi*m/1024)
    }
}

#define ASTRIDE 36
#define BSTRIDE_T 136   // Bs[k][n] layout (gemm_nn: C staged untransposed)
#define BSTRIDE_N 36    // Bs[n][k] layout (gemm_win: W staged untransposed)

// convert a float4 to tf32 bit-patterns packed in a uint4
__device__ __forceinline__ uint4 cvt4_tf32(float4 v) {
    uint4 u;
    CVT_TF32(u.x, v.x); CVT_TF32(u.y, v.y);
    CVT_TF32(u.z, v.z); CVT_TF32(u.w, v.w);
    return u;
}

// ---------------------------------------------------------------------
// Kernel 1 (tf32): M = A(4096x1024) @ C(1024x1024)  (flag: 0->g_Md, 1->g_Me)
// ---------------------------------------------------------------------
__global__ __launch_bounds__(256, 2) void gemm_nn_tf32(const float* __restrict__ A, int flag) {
    float* __restrict__ D = flag ? g_Me : g_Md;

    __shared__ unsigned As[128 * ASTRIDE];     // 18 KB (tf32 bits)
    __shared__ unsigned Bs[32 * BSTRIDE_T];    // 17 KB (tf32 bits)
    int tid = threadIdx.x;
    int brow = blockIdx.y, bcol = blockIdx.x;
    int warp = tid >> 5, lane = tid & 31;
    int wm = warp >> 2, wn = warp & 3;
    int fr = lane >> 2, fc = lane & 3;

    int arow = tid >> 1;
    int akh  = (tid & 1) * 16;
    const float* pA = A + (size_t)(brow * 128 + arow) * 1024 + akh;
    int bk  = tid >> 3;
    int bnq = (tid & 7) * 16;
    const float* pC = g_C + (size_t)bk * 1024 + bcol * 128 + bnq;

    float acc[16][4];
#pragma unroll
    for (int i = 0; i < 16; i++)
#pragma unroll
        for (int c = 0; c < 4; c++) acc[i][c] = 0.0f;

    float4 a_pre[4], b_pre[4];
#pragma unroll
    for (int q = 0; q < 4; q++) {
        a_pre[q] = *(const float4*)(pA + q * 4);
        b_pre[q] = *(const float4*)(pC + q * 4);
    }

    for (int kt = 0; kt < 32; kt++) {
#pragma unroll
        for (int q = 0; q < 4; q++)
            *(uint4*)&As[arow * ASTRIDE + akh + q * 4] = cvt4_tf32(a_pre[q]);
#pragma unroll
        for (int q = 0; q < 4; q++)
            *(uint4*)&Bs[bk * BSTRIDE_T + bnq + q * 4] = cvt4_tf32(b_pre[q]);
        __syncthreads();

        if (kt < 31) {
            pA += 32; pC += (size_t)32 * 1024;
#pragma unroll
            for (int q = 0; q < 4; q++) {
                a_pre[q] = *(const float4*)(pA + q * 4);
                b_pre[q] = *(const float4*)(pC + q * 4);
            }
        }

#pragma unroll
        for (int k8 = 0; k8 < 32; k8 += 8) {
            unsigned af[4][4];
#pragma unroll
            for (int mt = 0; mt < 4; mt++) {
                int rb = wm * 64 + mt * 16;
                af[mt][0] = As[(rb + fr)     * ASTRIDE + k8 + fc];
                af[mt][1] = As[(rb + fr + 8) * ASTRIDE + k8 + fc];
                af[mt][2] = As[(rb + fr)     * ASTRIDE + k8 + fc + 4];
                af[mt][3] = As[(rb + fr + 8) * ASTRIDE + k8 + fc + 4];
            }
            unsigned bf[4][2];
#pragma unroll
            for (int nt = 0; nt < 4; nt++) {
                int cb = wn * 32 + nt * 8 + fr;
                bf[nt][0] = Bs[(k8 + fc)     * BSTRIDE_T + cb];
                bf[nt][1] = Bs[(k8 + fc + 4) * BSTRIDE_T + cb];
            }
#pragma unroll
            for (int mt = 0; mt < 4; mt++)
#pragma unroll
                for (int nt = 0; nt < 4; nt++) {
                    float* c = acc[mt * 4 + nt];
                    asm volatile(
                        "mma.sync.aligned.m16n8k8.row.col.f32.tf32.tf32.f32 "
                        "{%0,%1,%2,%3}, {%4,%5,%6,%7}, {%8,%9}, {%0,%1,%2,%3};"
                        : "+f"(c[0]), "+f"(c[1]), "+f"(c[2]), "+f"(c[3])
                        : "r"(af[mt][0]), "r"(af[mt][1]), "r"(af[mt][2]), "r"(af[mt][3]),
                          "r"(bf[nt][0]), "r"(bf[nt][1]));
                }
        }
        __syncthreads();
    }

#pragma unroll
    for (int mt = 0; mt < 4; mt++) {
#pragma unroll
        for (int nt = 0; nt < 4; nt++) {
            const float* c = acc[mt * 4 + nt];
            int row = brow * 128 + wm * 64 + mt * 16 + fr;
            int col = bcol * 128 + wn * 32 + nt * 8 + 2 * fc;
            D[(size_t)row * KWIN + col]           = c[0];
            D[(size_t)row * KWIN + col + 1]       = c[1];
            D[(size_t)(row + 8) * KWIN + col]     = c[2];
            D[(size_t)(row + 8) * KWIN + col + 1] = c[3];
        }
    }
}

// ---------------------------------------------------------------------
// Kernel 2 (tf32): G[t][r] = sum_n window(t,n)*M[r][n] + bias[r]
// ---------------------------------------------------------------------
__global__ __launch_bounds__(256, 2) void gemm_win_tf32(const float* __restrict__ x,
                                                        const float* __restrict__ bias,
                                                        int flag, int Mrows) {
    const float* __restrict__ W = flag ? g_Me : g_Md;   // 4096 x 1024
    float* __restrict__ D = flag ? g_Ge : g_Gd;

    __shared__ unsigned As[128 * ASTRIDE];     // 18 KB (tf32 bits)
    __shared__ unsigned Bs[128 * BSTRIDE_N];   // 18 KB (tf32 bits)
    int tid = threadIdx.x;
    int brow = blockIdx.y, bcol = blockIdx.x;
    int warp = tid >> 5, lane = tid & 31;
    int wm = warp >> 2, wn = warp & 3;
    int fr = lane >> 2, fc = lane & 3;

    int arow = tid >> 1;
    int akh  = (tid & 1) * 16;
    int trow = brow * 128 + arow;
    bool av = trow < Mrows;
    const float* pA = x;
    if (av) {
        int s = trow / 63;
        int w = trow - s * 63;
        pA = x + (size_t)s * TSAMP + (size_t)w * WSTRIDE + akh;
    }
    int bn  = tid & 127;
    int bkh = (tid >> 7) * 16;
    const float* pW = W + (size_t)(bcol * 128 + bn) * 1024 + bkh;

    float acc[16][4];
#pragma unroll
    for (int i = 0; i < 16; i++)
#pragma unroll
        for (int c = 0; c < 4; c++) acc[i][c] = 0.0f;

    const float4 z4 = make_float4(0.f, 0.f, 0.f, 0.f);
    float4 a_pre[4], b_pre[4];
#pragma unroll
    for (int q = 0; q < 4; q++) {
        a_pre[q] = av ? *(const float4*)(pA + q * 4) : z4;
        b_pre[q] = *(const float4*)(pW + q * 4);
    }

    for (int kt = 0; kt < 32; kt++) {
#pragma unroll
        for (int q = 0; q < 4; q++)
            *(uint4*)&As[arow * ASTRIDE + akh + q * 4] = cvt4_tf32(a_pre[q]);
#pragma unroll
        for (int q = 0; q < 4; q++)
            *(uint4*)&Bs[bn * BSTRIDE_N + bkh + q * 4] = cvt4_tf32(b_pre[q]);
        __syncthreads();

        if (kt < 31) {
            pA += 32; pW += 32;
#pragma unroll
            for (int q = 0; q < 4; q++) {
                a_pre[q] = av ? *(const float4*)(pA + q * 4) : z4;
                b_pre[q] = *(const float4*)(pW + q * 4);
            }
        }

#pragma unroll
        for (int k8 = 0; k8 < 32; k8 += 8) {
            unsigned af[4][4];
#pragma unroll
            for (int mt = 0; mt < 4; mt++) {
                int rb = wm * 64 + mt * 16;
                af[mt][0] = As[(rb + fr)     * ASTRIDE + k8 + fc];
                af[mt][1] = As[(rb + fr + 8) * ASTRIDE + k8 + fc];
                af[mt][2] = As[(rb + fr)     * ASTRIDE + k8 + fc + 4];
                af[mt][3] = As[(rb + fr + 8) * ASTRIDE + k8 + fc + 4];
            }
            unsigned bf[4][2];
#pragma unroll
            for (int nt = 0; nt < 4; nt++) {
                int cb = wn * 32 + nt * 8 + fr;
                bf[nt][0] = Bs[cb * BSTRIDE_N + k8 + fc];
                bf[nt][1] = Bs[cb * BSTRIDE_N + k8 + fc + 4];
            }
#pragma unroll
            for (int mt = 0; mt < 4; mt++)
#pragma unroll
                for (int nt = 0; nt < 4; nt++) {
                    float* c = acc[mt * 4 + nt];
                    asm volatile(
                        "mma.sync.aligned.m16n8k8.row.col.f32.tf32.tf32.f32 "
                        "{%0,%1,%2,%3}, {%4,%5,%6,%7}, {%8,%9}, {%0,%1,%2,%3};"
                        : "+f"(c[0]), "+f"(c[1]), "+f"(c[2]), "+f"(c[3])
                        : "r"(af[mt][0]), "r"(af[mt][1]), "r"(af[mt][2]), "r"(af[mt][3]),
                          "r"(bf[nt][0]), "r"(bf[nt][1]));
                }
        }
        __syncthreads();
    }

#pragma unroll
    for (int mt = 0; mt < 4; mt++) {
#pragma unroll
        for (int nt = 0; nt < 4; nt++) {
            const float* c = acc[mt * 4 + nt];
            int row = brow * 128 + wm * 64 + mt * 16 + fr;
            int col = bcol * 128 + wn * 32 + nt * 8 + 2 * fc;
            float b0v = bias[col], b1v = bias[col + 1];
            if (row < Mrows) {
                D[(size_t)row * G4 + col]     = c[0] + b0v;
                D[(size_t)row * G4 + col + 1] = c[1] + b1v;
            }
            if (row + 8 < Mrows) {
                D[(size_t)(row + 8) * G4 + col]     = c[2] + b0v;
                D[(size_t)(row + 8) * G4 + col + 1] = c[3] + b1v;
            }
        }
    }
}

// ---------------------------------------------------------------------
// Persistent sequential kernel — R16 scheme with arbiter-aware publish:
//  * publisher moved to WARP 7 (hi-wid-first arbiter => stores issue
//    immediately after the stage barrier, not behind spinning warps)
//  * pre-poll delay spin uses __nanosleep so waiting warps vacate
//    issue slots during the publish window
// ---------------------------------------------------------------------
__device__ __forceinline__ float wredsum(float v) {
    v += __shfl_xor_sync(0xffffffffu, v, 16);
    v += __shfl_xor_sync(0xffffffffu, v, 8);
    v += __shfl_xor_sync(0xffffffffu, v, 4);
    v += __shfl_xor_sync(0xffffffffu, v, 2);
    v += __shfl_xor_sync(0xffffffffu, v, 1);
    return v;
}
__device__ __forceinline__ float sigm(float x) {
    return __fdividef(1.0f, 1.0f + __expf(-x));
}
__device__ __forceinline__ float ftanh(float x) {
    return 2.0f * __fdividef(1.0f, 1.0f + __expf(-2.0f * x)) - 1.0f;
}
__device__ __forceinline__ void stcg4(float2* p, float h0, float h1, float et) {
    asm volatile("st.global.cg.v4.f32 [%0], {%1,%2,%3,%4};"
                 :: "l"(p), "f"(h0), "f"(et), "f"(h1), "f"(et) : "memory");
}
__device__ __forceinline__ float4 ldcg4(const float2* p) {
    float4 v;
    asm volatile("ld.global.cg.v4.f32 {%0,%1,%2,%3}, [%4];"
                 : "=f"(v.x), "=f"(v.y), "=f"(v.z), "=f"(v.w) : "l"(p) : "memory");
    return v;
}

__global__ __launch_bounds__(TPB, 1) void seq_kernel(
    const float* __restrict__ Whh_e,
    const float* __restrict__ Wm1, const float* __restrict__ bm1,
    const float* __restrict__ Wm2, const float* __restrict__ bm2,
    const float* __restrict__ Whh_d)
{
    __shared__ float sh[2][H];
    __shared__ float stage[8];
    int tid  = threadIdx.x;
    int lane = tid & 31;
    int warp = tid >> 5;
    int j = blockIdx.x * 8 + warp;
    int ep = 0;
    bool own = ((tid >> 1) == blockIdx.x);
    bool pub = (tid >= 224 && tid < 228);   // warp 7: highest arbiter priority

    ull wr2[64];
#pragma unroll
    for (int q = 0; q < 4; q++) {
        const ull* row = (const ull*)(Whh_d + (size_t)(q * H + j) * H);
#pragma unroll
        for (int i = 0; i < 16; i++)
            wr2[q * 16 + i] = row[lane + 32 * i];
    }

#pragma unroll
    for (int u = 0; u < 4; u++) sh[0][tid + 256 * u] = 0.0f;
    __syncthreads();
    const float* cur = sh[0];

    auto sync_collect = [&](float hnew) {
        if (lane == 0) stage[warp] = hnew;
        __syncthreads();                 // load-bearing: closes reads of sh[nb]
        ep++;
        int nb = ep & 1;
        float et = __int_as_float(ep);
        unsigned long long t0 = clock64();
        if (pub) {                       // warp 7 publishes the 64B line
            int q = tid - 224;
            stcg4(&g_hep[nb][blockIdx.x * 8 + q * 2],
                  stage[q * 2], stage[q * 2 + 1], et);
        }

        float h0, h1, h2, h3;
        if (own) {
            int off = (tid & 1) * 4;
            h0 = stage[off]; h1 = stage[off + 1];
            h2 = stage[off + 2]; h3 = stage[off + 3];
        } else {
            // sleep (not spin) until data is expected visible in L2 —
            // vacates issue slots during the publish window
            while (clock64() - t0 < POLL_DELAY) __nanosleep(32);
            const float2* p = &g_hep[nb][tid * 4];
            float4 va, vb;
            unsigned pend = 3u;
            do {
                if (pend & 1u) {
                    va = ldcg4(p);
                    if (__float_as_int(va.y) == ep && __float_as_int(va.w) == ep)
                        pend &= ~1u;
                }
                if (pend & 2u) {
                    vb = ldcg4(p + 2);
                    if (__float_as_int(vb.y) == ep && __float_as_int(vb.w) == ep)
                        pend &= ~2u;
                }
            } while (pend);
            h0 = va.x; h1 = va.z; h2 = vb.x; h3 = vb.z;
        }
        ((float4*)sh[nb])[tid] = make_float4(h0, h1, h2, h3);
        __syncthreads();
        cur = sh[nb];
    };

    // ================= encoder (token 0 only), 63 steps =================
    float c = 0.0f;
    const float* we0 = Whh_e + (size_t)(0 * H + j) * H + lane;
    const float* we1 = Whh_e + (size_t)(1 * H + j) * H + lane;
    const float* we2 = Whh_e + (size_t)(2 * H + j) * H + lane;
    const float* we3 = Whh_e + (size_t)(3 * H + j) * H + lane;

    for (int t = 0; t < NW; t++) {
        float a0 = 0.f, a1 = 0.f, a2 = 0.f, a3 = 0.f;
#pragma unroll
        for (int k = 0; k < 32; k++) {
            float hv = cur[k * 32 + lane];
            a0 += we0[k * 32] * hv;
            a1 += we1[k * 32] * hv;
            a2 += we2[k * 32] * hv;
            a3 += we3[k * 32] * hv;
        }
        a0 = wredsum(a0); a1 = wredsum(a1); a2 = wredsum(a2); a3 = wredsum(a3);
        const float* ge = g_Ge + (size_t)t * G4;
        float iv = sigm(a0 + ge[j]);
        float fv = sigm(a1 + ge[H + j]);
        float gv = ftanh(a2 + ge[2 * H + j]);
        float ov = sigm(a3 + ge[3 * H + j]);
        c = fv * c + iv * gv;
        float hnew = ov * ftanh(c);
        sync_collect(hnew);
    }

    // ================= mid MLP ================================
    {
        float a = 0.f;
        const float* w = Wm1 + (size_t)j * H + lane;
#pragma unroll
        for (int k = 0; k < 32; k++) a += w[k * 32] * cur[k * 32 + lane];
        a = wredsum(a) + bm1[j];
        a = fmaxf(a, 0.0f);
        sync_collect(a);
    }
    {
        float a = 0.f;
        const float* w = Wm2 + (size_t)j * H + lane;
#pragma unroll
        for (int k = 0; k < 32; k++) a += w[k * 32] * cur[k * 32 + lane];
        a = wredsum(a) + bm2[j];
        a = ftanh(a);
        sync_collect(a);
    }

    // ================= decoder: 8064 steps, h0 = c0 = h_mid ==============
    float c2 = cur[j];
    float gi = g_Gd[j], gf = g_Gd[H + j], gg = g_Gd[2 * H + j], go = g_Gd[3 * H + j];
    int wcnt = 0, tok = 0;

    for (int t = 0; t < ND; t++) {
        int tn = (t + 1 < ND) ? (t + 1) : t;
        const float* gp = g_Gd + (size_t)tn * G4;
        float ngi = gp[j], ngf = gp[H + j], ngg = gp[2 * H + j], ngo = gp[3 * H + j];

        const ull* hp = (const ull*)cur;
        ull s0 = 0ull, s1 = 0ull, s2 = 0ull, s3 = 0ull;
#pragma unroll
        for (int i = 0; i < 16; i++) {
            ull hv = hp[lane + 32 * i];
            FFMA2(s0, wr2[i],      hv);
            FFMA2(s1, wr2[16 + i], hv);
            FFMA2(s2, wr2[32 + i], hv);
            FFMA2(s3, wr2[48 + i], hv);
        }
        float a0, a1, a2, a3, xl, xh;
        UNPK2(xl, xh, s0); a0 = xl + xh;
        UNPK2(xl, xh, s1); a1 = xl + xh;
        UNPK2(xl, xh, s2); a2 = xl + xh;
        UNPK2(xl, xh, s3); a3 = xl + xh;
        a0 = wredsum(a0); a1 = wredsum(a1); a2 = wredsum(a2); a3 = wredsum(a3);
        float iv = sigm(a0 + gi);
        float fv = sigm(a1 + gf);
        float gv = ftanh(a2 + gg);
        float ov = sigm(a3 + go);
        c2 = fv * c2 + iv * gv;
        float hnew = ov * ftanh(c2);
        gi = ngi; gf = ngf; gg = ngg; go = ngo;

        if (++wcnt == 63) {
            wcnt = 0;
            if (lane == 0) g_hsave[(size_t)tok * H + j] = hnew;
            tok++;
        }

        sync_collect(hnew);
    }
}

// ---------------------------------------------------------------------
// Final: logits = Hsave @ Wo^T + bo, fused log_softmax, 1 CTA per token
// ---------------------------------------------------------------------
__global__ __launch_bounds__(256) void lsm_kernel(const float* __restrict__ Wo,
                                                  const float* __restrict__ bo,
                                                  float* __restrict__ out) {
    __shared__ float hrow[H];
    __shared__ float sred[8];
    int tid = threadIdx.x, lane = tid & 31, warp = tid >> 5;

    *(float4*)&hrow[tid * 4] = *(const float4*)&g_hsave[(size_t)blockIdx.x * H + tid * 4];
    __syncthreads();

    const ull* hp = (const ull*)hrow;
    float v[4];
#pragma unroll
    for (int u = 0; u < 4; u++) {
        int cidx = tid + 256 * u;
        const ull* wp = (const ull*)(Wo + (size_t)cidx * H);
        ull acc = 0ull;
#pragma unroll 8
        for (int k2 = 0; k2 < 512; k2++) FFMA2(acc, wp[k2], hp[k2]);
        float lo, hi; UNPK2(lo, hi, acc);
        v[u] = lo + hi + bo[cidx];
    }

    float m = -1e30f;
#pragma unroll
    for (int u = 0; u < 4; u++) m = fmaxf(m, v[u]);
#pragma unroll
    for (int off = 16; off; off >>= 1) m = fmaxf(m, __shfl_xor_sync(0xffffffffu, m, off));
    if (lane == 0) sred[warp] = m;
    __syncthreads();
    if (tid == 0) {
        float mm = sred[0];
        for (int w = 1; w < 8; w++) mm = fmaxf(mm, sred[w]);
        sred[0] = mm;
    }
    __syncthreads();
    m = sred[0];
    __syncthreads();
    float s = 0.f;
#pragma unroll
    for (int u = 0; u < 4; u++) s += __expf(v[u] - m);
#pragma unroll
    for (int off = 16; off; off >>= 1) s += __shfl_xor_sync(0xffffffffu, s, off);
    if (lane == 0) sred[warp] = s;
    __syncthreads();
    if (tid == 0) {
        float st = 0.f;
        for (int w = 0; w < 8; w++) st += sred[w];
        sred[0] = st;
    }
    __syncthreads();
    float l = m + logf(sred[0]);
    float* z = out + (size_t)blockIdx.x * H;
#pragma unroll
    for (int u = 0; u < 4; u++) z[tid + 256 * u] = v[u] - l;
}

// ---------------------------------------------------------------------
extern "C" void kernel_launch(void* const* d_in, const int* in_sizes, int n_in,
                              void* d_out, int out_size) {
    const float* x     = (const float*)d_in[0];
    const float* Wih_e = (const float*)d_in[1];
    const float* Whh_e = (const float*)d_in[2];
    const float* b_e   = (const float*)d_in[3];
    const float* Wm1   = (const float*)d_in[4];
    const float* bm1   = (const float*)d_in[5];
    const float* Wm2   = (const float*)d_in[6];
    const float* bm2   = (const float*)d_in[7];
    const float* Wih_d = (const float*)d_in[8];
    const float* Whh_d = (const float*)d_in[9];
    const float* b_d   = (const float*)d_in[10];
    const float* Wo    = (const float*)d_in[11];
    const float* bo    = (const float*)d_in[12];
    float* out = (float*)d_out;

    // 0) cos matrix + tag reset (both needed every replay)
    fill_C<<<4096, 256>>>();

    // 1) fold DFT into input projections via tf32 tensor cores
    gemm_nn_tf32<<<dim3(KWIN / 128, G4 / 128), 256>>>(Wih_d, 0);  // -> g_Md
    gemm_nn_tf32<<<dim3(KWIN / 128, G4 / 128), 256>>>(Wih_e, 1);  // -> g_Me

    // 2) precompute all input gates via tf32 tensor cores
    gemm_win_tf32<<<dim3(G4 / 128, ND / 128), 256>>>(x, b_d, 0, ND);  // -> g_Gd
    gemm_win_tf32<<<dim3(G4 / 128, 1),        256>>>(x, b_e, 1, NW);  // -> g_Ge

    // 3) sequential encoder + MLP + decoder (persistent, arbiter-aware sync)
    seq_kernel<<<NCTA, TPB>>>(Whh_e, Wm1, bm1, Wm2, bm2, Whh_d);

    // 4) logits GEMM + log_softmax per token
    lsm_kernel<<<NTOK, 256>>>(Wo, bo, out);
}